// round 2
// baseline (speedup 1.0000x reference)
#include <cuda_runtime.h>
#include <cstdint>

// Problem dims (fixed by the benchmark)
#define LL 4096
#define HH 512
#define NN 16
#define RR 32

// Scratch (device globals — no allocation allowed)
__device__ float g_uT[HH * LL];     // u transposed [h][l]
__device__ float g_dtu[LL * RR];    // dt_u [l][r]
__device__ float g_dtT[HH * LL];    // dt   [h][l]
__device__ float g_rdtT[HH * LL];   // 1/dt [h][l]
__device__ float g_yT[HH * LL];     // y    [h][l]

// ---------------------------------------------------------------------------
// K0: transpose u [L][H] -> g_uT [H][L]
// ---------------------------------------------------------------------------
__global__ void k0_transpose_u(const float* __restrict__ u) {
    __shared__ float t[32][33];
    int h0 = blockIdx.x * 32, l0 = blockIdx.y * 32;
    int x = threadIdx.x, y = threadIdx.y;
#pragma unroll
    for (int i = 0; i < 32; i += 8)
        t[y + i][x] = u[(l0 + y + i) * HH + h0 + x];
    __syncthreads();
#pragma unroll
    for (int i = 0; i < 32; i += 8)
        g_uT[(h0 + y + i) * LL + l0 + x] = t[x][y + i];
}

// ---------------------------------------------------------------------------
// K1a: dt_u[l][r] = sum_h u[l][h] * xproj_w[r][h]
// One block per l (256 thr = 8 warps); warp w computes r = 4w..4w+3 via
// float4 lanes-over-h dot + shfl butterfly reduce.
// ---------------------------------------------------------------------------
__global__ void k1a_dtu(const float* __restrict__ u, const float* __restrict__ xw) {
    int l = blockIdx.x;
    int wid = threadIdx.x >> 5, lane = threadIdx.x & 31;
    const float4* u4 = (const float4*)(u + l * HH);
    float acc0 = 0.f, acc1 = 0.f, acc2 = 0.f, acc3 = 0.f;
#pragma unroll
    for (int i = 0; i < 4; i++) {
        float4 va = u4[i * 32 + lane];
        const float4* w0 = (const float4*)(xw + (wid * 4 + 0) * HH);
        const float4* w1 = (const float4*)(xw + (wid * 4 + 1) * HH);
        const float4* w2 = (const float4*)(xw + (wid * 4 + 2) * HH);
        const float4* w3 = (const float4*)(xw + (wid * 4 + 3) * HH);
        float4 a = w0[i * 32 + lane];
        float4 b = w1[i * 32 + lane];
        float4 c = w2[i * 32 + lane];
        float4 d = w3[i * 32 + lane];
        acc0 += va.x * a.x + va.y * a.y + va.z * a.z + va.w * a.w;
        acc1 += va.x * b.x + va.y * b.y + va.z * b.z + va.w * b.w;
        acc2 += va.x * c.x + va.y * c.y + va.z * c.z + va.w * c.w;
        acc3 += va.x * d.x + va.y * d.y + va.z * d.z + va.w * d.w;
    }
#pragma unroll
    for (int d = 16; d > 0; d >>= 1) {
        acc0 += __shfl_xor_sync(0xFFFFFFFFu, acc0, d);
        acc1 += __shfl_xor_sync(0xFFFFFFFFu, acc1, d);
        acc2 += __shfl_xor_sync(0xFFFFFFFFu, acc2, d);
        acc3 += __shfl_xor_sync(0xFFFFFFFFu, acc3, d);
    }
    if (lane == 0) {
        float* o = g_dtu + l * RR + wid * 4;
        o[0] = acc0; o[1] = acc1; o[2] = acc2; o[3] = acc3;
    }
}

// ---------------------------------------------------------------------------
// K1b: dt[l][h] = softplus( sum_r dt_u[l][r]*dt_w[h][r] + dt_b[h] )
// Writes transposed dtT[h][l] and rdtT[h][l] = 1/dt, coalesced.
// Block: 256 l x 64 h; grid (16, 8).
// ---------------------------------------------------------------------------
__global__ void k1b_dt(const float* __restrict__ dtw, const float* __restrict__ dtb) {
    __shared__ float  sdtu[256 * 36];
    __shared__ float4 sdtw[64 * 8];
    __shared__ float  sdtb[64];
    int l0 = blockIdx.x * 256, h0 = blockIdx.y * 64;
    int tid = threadIdx.x;
    for (int k = tid; k < 256 * 32; k += 256) {
        int l = k >> 5, r = k & 31;
        sdtu[l * 36 + r] = g_dtu[(l0 + l) * RR + r];
    }
    for (int k = tid; k < 64 * 8; k += 256)
        sdtw[k] = ((const float4*)dtw)[h0 * 8 + k];
    if (tid < 64) sdtb[tid] = dtb[h0 + tid];
    __syncthreads();

    float4 rowv[8];
#pragma unroll
    for (int j = 0; j < 8; j++)
        rowv[j] = *(const float4*)(&sdtu[tid * 36 + j * 4]);

    for (int h = 0; h < 64; ++h) {
        float acc = sdtb[h];
#pragma unroll
        for (int j = 0; j < 8; j++) {
            float4 w = sdtw[h * 8 + j];
            acc += rowv[j].x * w.x + rowv[j].y * w.y + rowv[j].z * w.z + rowv[j].w * w.w;
        }
        float dt = (acc > 20.f) ? acc : log1pf(__expf(acc));
        int o = (h0 + h) * LL + l0 + tid;
        g_dtT[o]  = dt;
        g_rdtT[o] = __frcp_rn(dt);
    }
}

// ---------------------------------------------------------------------------
// K2: fused ZOH discretization + linear-recurrence scan + C-contraction.
// Block = one h (512 thr, warp w <-> n=w). Lanes hold 4 consecutive l per
// tile (128 l), warp Kogge-Stone scan on (A,b) transforms; cross-n reduce in
// smem every 512 l.
// ---------------------------------------------------------------------------
#define LPAD 520
__global__ void __launch_bounds__(512, 2)
k2_scan(const float* __restrict__ A_log, const float* __restrict__ A_im,
        const float* __restrict__ Bp, const float* __restrict__ Cp,
        const float* __restrict__ Dp) {
    __shared__ float sy[NN * LPAD];
    int h = blockIdx.x;
    int tid = threadIdx.x, wid = tid >> 5, lane = tid & 31;
    int idx = h * NN + wid;

    float Are = -__expf(A_log[idx]);
    float Aim = A_im[idx];
    float Br = Bp[2 * idx], Bi = Bp[2 * idx + 1];
    float Cr = Cp[2 * idx], Ci = Cp[2 * idx + 1];
    float Dh = Dp[h];
    float invA2 = 1.0f / (Are * Are + Aim * Aim);
    float Gr = (Br * Are + Bi * Aim) * invA2;   // G = Bc*conj(A)/|A|^2
    float Gi = (Bi * Are - Br * Aim) * invA2;

    const float* uRow = g_uT + h * LL;
    const float* dtRow = g_dtT + h * LL;
    const float* rdtRow = g_rdtT + h * LL;
    float* yRow = g_yT + h * LL;

    float cr = 0.f, ci = 0.f;  // running h-state (carry)

    for (int sup = 0; sup < 8; ++sup) {
#pragma unroll
        for (int tile = 0; tile < 4; ++tile) {
            int l0 = sup * 512 + tile * 128;
            int e0 = l0 + lane * 4;
            float4 dt4 = *(const float4*)(dtRow + e0);
            float4 rdt4 = *(const float4*)(rdtRow + e0);
            float4 u4 = *(const float4*)(uRow + e0);

            float Abr[4], Abi[4], ubr[4], ubi[4];
            {
                float dts[4] = {dt4.x, dt4.y, dt4.z, dt4.w};
                float rds[4] = {rdt4.x, rdt4.y, rdt4.z, rdt4.w};
                float uvs[4] = {u4.x, u4.y, u4.z, u4.w};
#pragma unroll
                for (int j = 0; j < 4; j++) {
                    float dtv = dts[j];
                    float zr = dtv * Are, zi = dtv * Aim;
                    float er = __expf(zr);
                    float s, c;
                    __sincosf(zi, &s, &c);
                    float ar = er * c, ai = er * s;     // A_bar
                    float t = uvs[j] * rds[j];           // u/dt
                    float wr = ar - 1.0f, wi = ai;       // A_bar - 1
                    float p = t * wr, q = t * wi;
                    Abr[j] = ar; Abi[j] = ai;
                    ubr[j] = p * Gr - q * Gi;            // ub = (u/dt)(Ab-1)G
                    ubi[j] = p * Gi + q * Gr;
                }
            }

            // Thread-segment aggregate transform: h -> P*h + s
            float Pr = Abr[0], Pi = Abi[0], sr = ubr[0], si = ubi[0];
#pragma unroll
            for (int j = 1; j < 4; j++) {
                float nPr = Pr * Abr[j] - Pi * Abi[j];
                float nPi = Pr * Abi[j] + Pi * Abr[j];
                float nsr = sr * Abr[j] - si * Abi[j] + ubr[j];
                float nsi = sr * Abi[j] + si * Abr[j] + ubi[j];
                Pr = nPr; Pi = nPi; sr = nsr; si = nsi;
            }

            // Warp inclusive scan on transforms (combine(left, right))
            float iAr = Pr, iAi = Pi, ibr = sr, ibi = si;
#pragma unroll
            for (int d = 1; d < 32; d <<= 1) {
                float oAr = __shfl_up_sync(0xFFFFFFFFu, iAr, d);
                float oAi = __shfl_up_sync(0xFFFFFFFFu, iAi, d);
                float obr = __shfl_up_sync(0xFFFFFFFFu, ibr, d);
                float obi = __shfl_up_sync(0xFFFFFFFFu, ibi, d);
                if (lane >= d) {
                    float nAr = oAr * iAr - oAi * iAi;
                    float nAi = oAr * iAi + oAi * iAr;
                    float nbr = iAr * obr - iAi * obi + ibr;
                    float nbi = iAr * obi + iAi * obr + ibi;
                    iAr = nAr; iAi = nAi; ibr = nbr; ibi = nbi;
                }
            }

            // Exclusive prefix for this lane, applied to carry -> h_pre
            float eAr = __shfl_up_sync(0xFFFFFFFFu, iAr, 1);
            float eAi = __shfl_up_sync(0xFFFFFFFFu, iAi, 1);
            float ebr = __shfl_up_sync(0xFFFFFFFFu, ibr, 1);
            float ebi = __shfl_up_sync(0xFFFFFFFFu, ibi, 1);
            if (lane == 0) { eAr = 1.f; eAi = 0.f; ebr = 0.f; ebi = 0.f; }
            float hr = eAr * cr - eAi * ci + ebr;
            float hi = eAr * ci + eAi * cr + ebi;

            // Forward-walk the 4 elements, emit y = Re(C*h)
            float y0, y1, y2, y3;
            {
                float nhr, nhi;
                nhr = Abr[0] * hr - Abi[0] * hi + ubr[0];
                nhi = Abr[0] * hi + Abi[0] * hr + ubi[0];
                hr = nhr; hi = nhi; y0 = Cr * hr - Ci * hi;
                nhr = Abr[1] * hr - Abi[1] * hi + ubr[1];
                nhi = Abr[1] * hi + Abi[1] * hr + ubi[1];
                hr = nhr; hi = nhi; y1 = Cr * hr - Ci * hi;
                nhr = Abr[2] * hr - Abi[2] * hi + ubr[2];
                nhi = Abr[2] * hi + Abi[2] * hr + ubi[2];
                hr = nhr; hi = nhi; y2 = Cr * hr - Ci * hi;
                nhr = Abr[3] * hr - Abi[3] * hi + ubr[3];
                nhi = Abr[3] * hi + Abi[3] * hr + ubi[3];
                hr = nhr; hi = nhi; y3 = Cr * hr - Ci * hi;
            }
            *(float4*)(&sy[wid * LPAD + tile * 128 + lane * 4]) =
                make_float4(y0, y1, y2, y3);

            // Advance carry by whole-warp transform (lane 31 inclusive)
            float tAr = __shfl_sync(0xFFFFFFFFu, iAr, 31);
            float tAi = __shfl_sync(0xFFFFFFFFu, iAi, 31);
            float tbr = __shfl_sync(0xFFFFFFFFu, ibr, 31);
            float tbi = __shfl_sync(0xFFFFFFFFu, ibi, 31);
            float ncr = tAr * cr - tAi * ci + tbr;
            float nci = tAr * ci + tAi * cr + tbi;
            cr = ncr; ci = nci;
        }
        __syncthreads();
        {
            int l = sup * 512 + tid;
            float acc = 0.f;
#pragma unroll
            for (int n = 0; n < NN; n++) acc += sy[n * LPAD + tid];
            yRow[l] = fmaf(Dh, uRow[l], acc);
        }
        __syncthreads();
    }
}

// ---------------------------------------------------------------------------
// K3: transpose g_yT [H][L] -> out [L][H]
// ---------------------------------------------------------------------------
__global__ void k3_transpose_y(float* __restrict__ out) {
    __shared__ float t[32][33];
    int l0 = blockIdx.x * 32, h0 = blockIdx.y * 32;
    int x = threadIdx.x, y = threadIdx.y;
#pragma unroll
    for (int i = 0; i < 32; i += 8)
        t[y + i][x] = g_yT[(h0 + y + i) * LL + l0 + x];
    __syncthreads();
#pragma unroll
    for (int i = 0; i < 32; i += 8)
        out[(l0 + y + i) * HH + h0 + x] = t[x][y + i];
}

// ---------------------------------------------------------------------------
extern "C" void kernel_launch(void* const* d_in, const int* in_sizes, int n_in,
                              void* d_out, int out_size) {
    const float* u     = (const float*)d_in[0];
    const float* A_log = (const float*)d_in[1];
    const float* A_im  = (const float*)d_in[2];
    const float* Bp    = (const float*)d_in[3];
    const float* Cp    = (const float*)d_in[4];
    const float* D     = (const float*)d_in[5];
    const float* dtw   = (const float*)d_in[6];
    const float* dtb   = (const float*)d_in[7];
    const float* xw    = (const float*)d_in[8];
    float* out = (float*)d_out;

    dim3 tb(32, 8);
    k0_transpose_u<<<dim3(HH / 32, LL / 32), tb>>>(u);
    k1a_dtu<<<LL, 256>>>(u, xw);
    k1b_dt<<<dim3(LL / 256, HH / 64), 256>>>(dtw, dtb);
    k2_scan<<<HH, 512>>>(A_log, A_im, Bp, Cp, D);
    k3_transpose_y<<<dim3(LL / 32, HH / 32), tb>>>(out);
}